// round 4
// baseline (speedup 1.0000x reference)
#include <cuda_runtime.h>
#include <math.h>

// out[i] = sum_{j<512} r[batch[i][j]] + log(n_pos / n_neg)
// r (201KB) staged in SMEM; indices streamed from HBM with a 2-row
// software pipeline. 768 threads/CTA (24 warps) for better latency hiding
// while keeping the 65-reg pipeline spill-free (768*65 = 49.9K < 64K regs).

#define ROWS   16384
#define LEN    512
#define VOCAB  50257
#define NBLK   148
#define NTHR   768
#define NWARP  (NTHR / 32)           // 24
#define GWARPS (NBLK * NWARP)        // 3552

__device__ __forceinline__ void load_row(const int* __restrict__ batch,
                                         int row, int lane, int4* v)
{
    const int4* __restrict__ bp =
        reinterpret_cast<const int4*>(batch + (size_t)row * LEN);
#pragma unroll
    for (int i = 0; i < 4; i++)
        v[i] = bp[lane + 32 * i];
}

__global__ __launch_bounds__(NTHR, 1) void nb_pipe_kernel(
    const int* __restrict__ batch,
    const float* __restrict__ r,
    const int* __restrict__ n_pos,
    const int* __restrict__ n_neg,
    float* __restrict__ out)
{
    extern __shared__ float rs[];
    const int tid = threadIdx.x;

    // ---- Stage r into SMEM (float4) ----
    {
        const int n4 = VOCAB / 4;   // 12564
        const float4* __restrict__ r4 = reinterpret_cast<const float4*>(r);
        float4* rs4 = reinterpret_cast<float4*>(rs);
        for (int i = tid; i < n4; i += NTHR)
            rs4[i] = r4[i];
        if (tid == 0)
            rs[VOCAB - 1] = r[VOCAB - 1];
    }
    __syncthreads();

    const int warp = tid >> 5;
    const int lane = tid & 31;
    const int gw   = blockIdx.x * NWARP + warp;

    const float lp = logf((float)__ldg(n_pos) / (float)__ldg(n_neg));

    // ---- Pipelined pair loop ----
    int4 c0[4], c1[4];
    int  r0 = gw;
    bool v1 = false;

    if (r0 < ROWS) {
        load_row(batch, r0, lane, c0);
        if (r0 + GWARPS < ROWS) { load_row(batch, r0 + GWARPS, lane, c1); v1 = true; }
    }

    for (; r0 < ROWS; r0 += 2 * GWARPS) {
        // Prefetch next pair while we compute on the current one.
        int4 n0[4], n1[4];
        const int nr0 = r0 + 2 * GWARPS;
        bool nv1 = false;
        if (nr0 < ROWS) {
            load_row(batch, nr0, lane, n0);
            if (nr0 + GWARPS < ROWS) { load_row(batch, nr0 + GWARPS, lane, n1); nv1 = true; }
        }

        // Gather both rows, 2 accumulators each to break FADD chains.
        float a0 = 0.f, b0 = 0.f, a1 = 0.f, b1 = 0.f;
#pragma unroll
        for (int i = 0; i < 4; i++) {
            a0 += rs[c0[i].x];  b0 += rs[c0[i].y];
            a0 += rs[c0[i].z];  b0 += rs[c0[i].w];
        }
        if (v1) {
#pragma unroll
            for (int i = 0; i < 4; i++) {
                a1 += rs[c1[i].x];  b1 += rs[c1[i].y];
                a1 += rs[c1[i].z];  b1 += rs[c1[i].w];
            }
        }
        float s0 = a0 + b0;
        float s1 = a1 + b1;

        // Interleaved dual shuffle reductions (latencies overlap).
#pragma unroll
        for (int o = 16; o > 0; o >>= 1) {
            s0 += __shfl_xor_sync(0xFFFFFFFFu, s0, o);
            s1 += __shfl_xor_sync(0xFFFFFFFFu, s1, o);
        }

        if (lane == 0) {
            out[r0] = s0 + lp;
            if (v1) out[r0 + GWARPS] = s1 + lp;
        }

        // Rotate pipeline.
#pragma unroll
        for (int i = 0; i < 4; i++) { c0[i] = n0[i]; c1[i] = n1[i]; }
        v1 = nv1;
    }
}

extern "C" void kernel_launch(void* const* d_in, const int* in_sizes, int n_in,
                              void* d_out, int out_size)
{
    const int*   batch = (const int*)  d_in[0];
    const float* r     = (const float*)d_in[1];
    const int*   npos  = (const int*)  d_in[2];
    const int*   nneg  = (const int*)  d_in[3];
    float*       out   = (float*)      d_out;

    const int smem_bytes = ((VOCAB * 4 + 15) / 16) * 16;   // 201040 B

    static int configured = 0;
    if (!configured) {
        cudaFuncSetAttribute(nb_pipe_kernel,
                             cudaFuncAttributeMaxDynamicSharedMemorySize,
                             smem_bytes);
        configured = 1;
    }

    nb_pipe_kernel<<<NBLK, NTHR, smem_bytes>>>(batch, r, npos, nneg, out);
}

// round 5
// speedup vs baseline: 1.1604x; 1.1604x over previous
#include <cuda_runtime.h>
#include <math.h>
#include <stdint.h>

// out[i] = sum_{j<512} r[batch[i][j]] + log(n_pos / n_neg)
// r (201KB) staged into SMEM via TMA bulk copy (async) while all warps
// pre-issue TWO pairs of index-row loads; then a 2-row software pipeline
// gathers from SMEM. 148 CTAs x 512 threads (16 warps), spill-free.

#define ROWS   16384
#define LEN    512
#define VOCAB  50257
#define NBLK   148
#define NTHR   512
#define NWARP  (NTHR / 32)           // 16
#define GWARPS (NBLK * NWARP)        // 2368

#define RS_BYTES   (VOCAB * 4)               // 201028
#define RS_BULK    ((RS_BYTES / 16) * 16)    // 201024 (16B multiple for TMA)
#define MBAR_OFF   201040                    // 16B-aligned, after rs
#define SMEM_TOTAL (MBAR_OFF + 16)

__device__ __forceinline__ uint32_t smem_u32(const void* p) {
    uint32_t a;
    asm("{ .reg .u64 t; cvta.to.shared.u64 t, %1; cvt.u32.u64 %0, t; }"
        : "=r"(a) : "l"(p));
    return a;
}

__device__ __forceinline__ void load_row(const int* __restrict__ batch,
                                         int row, int lane, int4* v)
{
    const int4* __restrict__ bp =
        reinterpret_cast<const int4*>(batch + (size_t)row * LEN);
#pragma unroll
    for (int i = 0; i < 4; i++)
        v[i] = bp[lane + 32 * i];
}

__global__ __launch_bounds__(NTHR, 1) void nb_tma_kernel(
    const int* __restrict__ batch,
    const float* __restrict__ r,
    const int* __restrict__ n_pos,
    const int* __restrict__ n_neg,
    float* __restrict__ out)
{
    extern __shared__ float rs[];
    const int tid  = threadIdx.x;
    const int warp = tid >> 5;
    const int lane = tid & 31;
    const int gw   = blockIdx.x * NWARP + warp;

    char* smem_raw = reinterpret_cast<char*>(rs);
    const uint32_t mbar = smem_u32(smem_raw + MBAR_OFF);
    const uint32_t rs_s = smem_u32(smem_raw);

    // Init barrier + tail element (the 4 bytes TMA can't cover).
    if (tid == 0) {
        rs[VOCAB - 1] = r[VOCAB - 1];
        asm volatile("mbarrier.init.shared.b64 [%0], %1;" :: "r"(mbar), "r"(1) : "memory");
    }
    __syncthreads();

    // ---- Pre-issue index loads for TWO pairs (overlaps with staging) ----
    int r0 = gw;
    int4 c0[4], c1[4], n0[4], n1[4];
    bool cv1 = false, nv0 = false, nv1 = false;

    if (r0 < ROWS) {
        load_row(batch, r0, lane, c0);
        if (r0 + GWARPS < ROWS) { load_row(batch, r0 + GWARPS, lane, c1); cv1 = true; }
    }
    {
        const int nr = r0 + 2 * GWARPS;
        if (nr < ROWS) {
            load_row(batch, nr, lane, n0); nv0 = true;
            if (nr + GWARPS < ROWS) { load_row(batch, nr + GWARPS, lane, n1); nv1 = true; }
        }
    }

    // ---- TMA bulk staging of r into SMEM (4 chunks, one tx budget) ----
    if (tid == 0) {
        asm volatile("mbarrier.arrive.expect_tx.shared.b64 _, [%0], %1;"
                     :: "r"(mbar), "r"((uint32_t)RS_BULK) : "memory");
        const uint32_t chunk = RS_BULK / 4;     // 50256, 16B multiple
#pragma unroll
        for (int i = 0; i < 4; i++) {
            asm volatile(
                "cp.async.bulk.shared::cta.global.mbarrier::complete_tx::bytes "
                "[%0], [%1], %2, [%3];"
                :: "r"(rs_s + i * chunk),
                   "l"((const char*)r + i * chunk),
                   "r"(chunk), "r"(mbar)
                : "memory");
        }
    }

    const float lp = logf((float)__ldg(n_pos) / (float)__ldg(n_neg));

    // ---- Wait for r (acquire) ----
    {
        uint32_t done;
        asm volatile(
            "{ .reg .pred p;\n"
            "  mbarrier.try_wait.parity.acquire.cta.shared::cta.b64 p, [%1], %2;\n"
            "  selp.b32 %0, 1, 0, p; }"
            : "=r"(done) : "r"(mbar), "r"(0u) : "memory");
        if (!done) {
            asm volatile(
                "{ .reg .pred P1;\n"
                "WAIT_LOOP:\n"
                "  mbarrier.try_wait.parity.acquire.cta.shared::cta.b64 P1, [%0], %1, 0x989680;\n"
                "  @P1 bra.uni WAIT_DONE;\n"
                "  bra.uni WAIT_LOOP;\n"
                "WAIT_DONE: }"
                :: "r"(mbar), "r"(0u) : "memory");
        }
    }

    // ---- Pipelined pair loop (c = current pair, n = next pair in flight) ----
    while (r0 < ROWS) {
        float a0 = 0.f, b0 = 0.f, a1 = 0.f, b1 = 0.f;
#pragma unroll
        for (int i = 0; i < 4; i++) {
            a0 += rs[c0[i].x];  b0 += rs[c0[i].y];
            a0 += rs[c0[i].z];  b0 += rs[c0[i].w];
        }
        if (cv1) {
#pragma unroll
            for (int i = 0; i < 4; i++) {
                a1 += rs[c1[i].x];  b1 += rs[c1[i].y];
                a1 += rs[c1[i].z];  b1 += rs[c1[i].w];
            }
        }
        float s0 = a0 + b0;
        float s1 = a1 + b1;
#pragma unroll
        for (int o = 16; o > 0; o >>= 1) {
            s0 += __shfl_xor_sync(0xFFFFFFFFu, s0, o);
            s1 += __shfl_xor_sync(0xFFFFFFFFu, s1, o);
        }
        if (lane == 0) {
            out[r0] = s0 + lp;
            if (cv1) out[r0 + GWARPS] = s1 + lp;
        }

        // Rotate: n -> c (loads issued one full compute-pair ago).
#pragma unroll
        for (int i = 0; i < 4; i++) { c0[i] = n0[i]; c1[i] = n1[i]; }
        cv1 = nv1;
        r0 += 2 * GWARPS;
        if (!nv0) break;                 // rotated-in pair invalid -> done

        // Prefetch the pair after next.
        const int nr = r0 + 2 * GWARPS;
        nv0 = nv1 = false;
        if (nr < ROWS) {
            load_row(batch, nr, lane, n0); nv0 = true;
            if (nr + GWARPS < ROWS) { load_row(batch, nr + GWARPS, lane, n1); nv1 = true; }
        }
    }
}

extern "C" void kernel_launch(void* const* d_in, const int* in_sizes, int n_in,
                              void* d_out, int out_size)
{
    const int*   batch = (const int*)  d_in[0];
    const float* r     = (const float*)d_in[1];
    const int*   npos  = (const int*)  d_in[2];
    const int*   nneg  = (const int*)  d_in[3];
    float*       out   = (float*)      d_out;

    static int configured = 0;
    if (!configured) {
        cudaFuncSetAttribute(nb_tma_kernel,
                             cudaFuncAttributeMaxDynamicSharedMemorySize,
                             SMEM_TOTAL);
        configured = 1;
    }

    nb_tma_kernel<<<NBLK, NTHR, SMEM_TOTAL>>>(batch, r, npos, nneg, out);
}

// round 6
// speedup vs baseline: 1.3821x; 1.1910x over previous
#include <cuda_runtime.h>
#include <math.h>
#include <stdint.h>

// out[i] = sum_{j<512} r[batch[i][j]] + log(n_pos / n_neg)
// r (201KB) staged into SMEM via TMA while each warp pre-issues ALL SIX of
// its index rows (24 LDG.128 in flight). Each warp owns rows
// gw + k*GWARPS, k=0..5 (+ row 6 iff gw < 2176). 148 CTAs x 512 threads.

#define ROWS   16384
#define LEN    512
#define VOCAB  50257
#define NBLK   148
#define NTHR   512
#define NWARP  (NTHR / 32)           // 16
#define GWARPS (NBLK * NWARP)        // 2368;  ROWS = 6*GWARPS + 2176

#define RS_BYTES   (VOCAB * 4)               // 201028
#define RS_BULK    ((RS_BYTES / 16) * 16)    // 201024
#define MBAR_OFF   201040
#define SMEM_TOTAL (MBAR_OFF + 16)

__device__ __forceinline__ uint32_t smem_u32(const void* p) {
    uint32_t a;
    asm("{ .reg .u64 t; cvta.to.shared.u64 t, %1; cvt.u32.u64 %0, t; }"
        : "=r"(a) : "l"(p));
    return a;
}

__device__ __forceinline__ void load_row(const int* __restrict__ batch,
                                         int row, int lane, int4* v)
{
    const int4* __restrict__ bp =
        reinterpret_cast<const int4*>(batch + (size_t)row * LEN);
#pragma unroll
    for (int i = 0; i < 4; i++)
        v[i] = bp[lane + 32 * i];
}

// Gather + interleaved dual reduction for a pair of rows.
__device__ __forceinline__ void compute_pair(const float* __restrict__ rs,
                                             const int4* x, const int4* y,
                                             int lane, float lp,
                                             float* __restrict__ out,
                                             int row0, int row1)
{
    float a0 = 0.f, b0 = 0.f, a1 = 0.f, b1 = 0.f;
#pragma unroll
    for (int i = 0; i < 4; i++) {
        a0 += rs[x[i].x];  b0 += rs[x[i].y];
        a0 += rs[x[i].z];  b0 += rs[x[i].w];
        a1 += rs[y[i].x];  b1 += rs[y[i].y];
        a1 += rs[y[i].z];  b1 += rs[y[i].w];
    }
    float s0 = a0 + b0;
    float s1 = a1 + b1;
#pragma unroll
    for (int o = 16; o > 0; o >>= 1) {
        s0 += __shfl_xor_sync(0xFFFFFFFFu, s0, o);
        s1 += __shfl_xor_sync(0xFFFFFFFFu, s1, o);
    }
    if (lane == 0) {
        out[row0] = s0 + lp;
        out[row1] = s1 + lp;
    }
}

__global__ __launch_bounds__(NTHR, 1) void nb_deep_kernel(
    const int* __restrict__ batch,
    const float* __restrict__ r,
    const int* __restrict__ n_pos,
    const int* __restrict__ n_neg,
    float* __restrict__ out)
{
    extern __shared__ float rs[];
    const int tid  = threadIdx.x;
    const int warp = tid >> 5;
    const int lane = tid & 31;
    const int gw   = blockIdx.x * NWARP + warp;

    char* smem_raw = reinterpret_cast<char*>(rs);
    const uint32_t mbar = smem_u32(smem_raw + MBAR_OFF);
    const uint32_t rs_s = smem_u32(smem_raw);

    if (tid == 0) {
        rs[VOCAB - 1] = r[VOCAB - 1];
        asm volatile("mbarrier.init.shared.b64 [%0], %1;" :: "r"(mbar), "r"(1) : "memory");
    }
    __syncthreads();

    // ---- Pre-issue ALL six rows' index loads (24 LDG.128 per warp) ----
    int4 A[4], B[4], C[4], D[4], E[4], F[4];
    load_row(batch, gw + 0 * GWARPS, lane, A);
    load_row(batch, gw + 1 * GWARPS, lane, B);
    load_row(batch, gw + 2 * GWARPS, lane, C);
    load_row(batch, gw + 3 * GWARPS, lane, D);
    load_row(batch, gw + 4 * GWARPS, lane, E);
    load_row(batch, gw + 5 * GWARPS, lane, F);
    const bool has7 = (gw + 6 * GWARPS) < ROWS;   // gw < 2176

    // ---- TMA bulk staging of r into SMEM ----
    if (tid == 0) {
        asm volatile("mbarrier.arrive.expect_tx.shared.b64 _, [%0], %1;"
                     :: "r"(mbar), "r"((uint32_t)RS_BULK) : "memory");
        const uint32_t chunk = RS_BULK / 4;
#pragma unroll
        for (int i = 0; i < 4; i++) {
            asm volatile(
                "cp.async.bulk.shared::cta.global.mbarrier::complete_tx::bytes "
                "[%0], [%1], %2, [%3];"
                :: "r"(rs_s + i * chunk),
                   "l"((const char*)r + i * chunk),
                   "r"(chunk), "r"(mbar)
                : "memory");
        }
    }

    const float lp = logf((float)__ldg(n_pos) / (float)__ldg(n_neg));

    // ---- Wait for r (acquire) ----
    {
        uint32_t done;
        asm volatile(
            "{ .reg .pred p;\n"
            "  mbarrier.try_wait.parity.acquire.cta.shared::cta.b64 p, [%1], %2;\n"
            "  selp.b32 %0, 1, 0, p; }"
            : "=r"(done) : "r"(mbar), "r"(0u) : "memory");
        if (!done) {
            asm volatile(
                "{ .reg .pred P1;\n"
                "WAIT_LOOP:\n"
                "  mbarrier.try_wait.parity.acquire.cta.shared::cta.b64 P1, [%0], %1, 0x989680;\n"
                "  @P1 bra.uni WAIT_DONE;\n"
                "  bra.uni WAIT_LOOP;\n"
                "WAIT_DONE: }"
                :: "r"(mbar), "r"(0u) : "memory");
        }
    }

    // ---- Compute: three pairs + optional 7th row ----
    compute_pair(rs, A, B, lane, lp, out, gw + 0 * GWARPS, gw + 1 * GWARPS);

    // Row 6's loads reuse A's (now dead) registers; issued 2 pairs before use.
    int4 G[4];
    if (has7) load_row(batch, gw + 6 * GWARPS, lane, G);

    compute_pair(rs, C, D, lane, lp, out, gw + 2 * GWARPS, gw + 3 * GWARPS);
    compute_pair(rs, E, F, lane, lp, out, gw + 4 * GWARPS, gw + 5 * GWARPS);

    if (has7) {
        float a = 0.f, b = 0.f;
#pragma unroll
        for (int i = 0; i < 4; i++) {
            a += rs[G[i].x];  b += rs[G[i].y];
            a += rs[G[i].z];  b += rs[G[i].w];
        }
        float s = a + b;
#pragma unroll
        for (int o = 16; o > 0; o >>= 1)
            s += __shfl_xor_sync(0xFFFFFFFFu, s, o);
        if (lane == 0)
            out[gw + 6 * GWARPS] = s + lp;
    }
}

extern "C" void kernel_launch(void* const* d_in, const int* in_sizes, int n_in,
                              void* d_out, int out_size)
{
    const int*   batch = (const int*)  d_in[0];
    const float* r     = (const float*)d_in[1];
    const int*   npos  = (const int*)  d_in[2];
    const int*   nneg  = (const int*)  d_in[3];
    float*       out   = (float*)      d_out;

    static int configured = 0;
    if (!configured) {
        cudaFuncSetAttribute(nb_deep_kernel,
                             cudaFuncAttributeMaxDynamicSharedMemorySize,
                             SMEM_TOTAL);
        configured = 1;
    }

    nb_deep_kernel<<<NBLK, NTHR, SMEM_TOTAL>>>(batch, r, npos, nneg, out);
}